// round 14
// baseline (speedup 1.0000x reference)
#include <cuda_runtime.h>
#include <math.h>

#define Nn 8192
#define DIN 64
#define DHID 128
#define DE 16
#define NH 4
#define TOPK 7
#define EK (Nn*TOPK)
#define ET (EK+Nn)
#define HF (NH*DHID)
#define BNS 0.9999950000374997f

#define OUT0_OFF 0
#define OUT1_OFF (Nn*64)
#define EI_OFF (OUT1_OFF + Nn*16)
#define LL_OFF (EI_OFF + 2*ET)

// -------- device scratch (no allocs allowed) --------
__device__ float g_M[Nn*Nn];          // full symmetric score matrix (256 MiB)
__device__ float g_M1[Nn*128];        // per-row per-64col-tile maxes (4 MiB)
__device__ float g_emb[Nn*DE];
__device__ float g_P[Nn*DE];
__device__ int   g_sel[Nn*TOPK];
__device__ int   g_src[ET];
__device__ int   g_dst[ET];
__device__ int   g_val[ET];
__device__ float g_hlin[Nn*HF];
__device__ float g_asrc[Nn*NH];
__device__ float g_adst[Nn*NH];
__device__ float g_acc[Nn*HF];        // zeroed explicitly by k_zacc each layer
__device__ float g_den[Nn*NH];        // zeroed explicitly by k_zacc each layer
__device__ float g_h[Nn*DHID];

__device__ __forceinline__ float eluf(float x){ return x > 0.f ? x : expm1f(x); }

// sorted top-7 insert (descending value, ties -> lower index)
__device__ __forceinline__ void ins7(float (&tv)[TOPK], int (&tix)[TOPK], float v, int j){
  if (v > tv[TOPK-1] || (v == tv[TOPK-1] && j < tix[TOPK-1])){
    float cv = v; int ci = j;
    #pragma unroll
    for (int s = 0; s < TOPK; s++){
      bool bt = (cv > tv[s]) || (cv == tv[s] && ci < tix[s]);
      float nv = bt ? cv : tv[s]; int ni = bt ? ci : tix[s];
      cv = bt ? tv[s] : cv; ci = bt ? tix[s] : ci;
      tv[s] = nv; tix[s] = ni;
    }
  }
}

// warp-merge sorted per-lane lists -> global top-7 indices, write to selp
__device__ __forceinline__ void wmerge7(float (&tv)[TOPK], int (&tix)[TOPK],
                                        int lane, int* selp){
  #pragma unroll 1
  for (int k = 0; k < TOPK; k++){
    float bv = tv[0]; int bi = tix[0];
    #pragma unroll
    for (int m = 16; m; m >>= 1){
      float ov = __shfl_xor_sync(0xffffffffu, bv, m);
      int   oi = __shfl_xor_sync(0xffffffffu, bi, m);
      if (ov > bv || (ov == bv && oi < bi)){ bv = ov; bi = oi; }
    }
    if (lane == 0) selp[k] = bi;
    if (tv[0] == bv && tix[0] == bi){
      #pragma unroll
      for (int s = 0; s < TOPK-1; s++){ tv[s] = tv[s+1]; tix[s] = tix[s+1]; }
      tv[TOPK-1] = -3.4e38f; tix[TOPK-1] = 0x7fffffff;
    }
  }
}

// -------- zero accumulators (stateless per launch) --------
__global__ void __launch_bounds__(256) k_zacc(){
  int t = blockIdx.x*256 + threadIdx.x;
  float4* a4 = (float4*)g_acc;
  if (t < (Nn*HF)/4) a4[t] = make_float4(0.f, 0.f, 0.f, 0.f);
  if (t < Nn*NH) g_den[t] = 0.f;
}

// -------- fused initial MLP: x -> tmp128 -> emb, P  (32 rows/block) --------
__global__ void __launch_bounds__(256) k_lin12(const float* __restrict__ x,
    const float* __restrict__ w1, const float* __restrict__ b1,
    const float* __restrict__ g1, const float* __restrict__ be1,
    const float* __restrict__ w2, const float* __restrict__ b2,
    const float* __restrict__ g2, const float* __restrict__ be2,
    const float* __restrict__ lpA){
  __shared__ float xs[32][DIN+1];
  __shared__ float t128[32][DHID+1];
  __shared__ float es[32][DE+1];
  int r0 = blockIdx.x*32, tid = threadIdx.x;
  for (int idx = tid; idx < 32*DIN; idx += 256) xs[idx/DIN][idx%DIN] = x[r0*DIN + idx];
  __syncthreads();
  {
    int c = tid & 127, rg = tid >> 7;
    float acc[16];
    #pragma unroll
    for (int k = 0; k < 16; k++) acc[k] = 0.f;
    for (int d = 0; d < DIN; d++){
      float wv = w1[d*DHID + c];
      #pragma unroll
      for (int k = 0; k < 16; k++) acc[k] += xs[rg + 2*k][d]*wv;
    }
    float bv = b1[c], gv = g1[c], bev = be1[c];
    #pragma unroll
    for (int k = 0; k < 16; k++)
      t128[rg + 2*k][c] = eluf(gv*(acc[k] + bv)*BNS + bev);
  }
  __syncthreads();
  int rr = tid >> 4, cc = tid & 15;
  #pragma unroll
  for (int half = 0; half < 2; half++){
    int row = rr + 16*half;
    float a2 = b2[cc];
    #pragma unroll 8
    for (int d = 0; d < DHID; d++) a2 += t128[row][d]*w2[d*DE + cc];
    a2 = eluf(g2[cc]*a2*BNS + be2[cc]);
    es[row][cc] = a2;
    g_emb[(r0+row)*DE + cc] = a2;
  }
  __syncthreads();
  #pragma unroll
  for (int half = 0; half < 2; half++){
    int row = rr + 16*half;
    float p = 0.f;
    #pragma unroll
    for (int d = 0; d < DE; d++) p += es[row][d]*lpA[d*DE + cc];
    g_P[(r0+row)*DE + cc] = p;
  }
}

// -------- score tiles: upper-tri 64x64; write M (both), ll, tile-maxes M1 --------
__global__ void __launch_bounds__(256) k_score(float* __restrict__ out,
                                               const float* __restrict__ lp_b){
  int jt = blockIdx.x, it = blockIdx.y;
  if (it > jt) return;
  __shared__ float Pt[64][16];
  __shared__ float Es[16][68];
  __shared__ float ts[64][68];
  __shared__ float rmx[64];
  __shared__ float cmx[4][64];
  int i0 = it*64, j0 = jt*64;
  int t = threadIdx.x;
  const float4* pF = (const float4*)g_P;
  const float4* eF = (const float4*)g_emb;
  {
    int r = t >> 2, q = t & 3;
    *(float4*)&Pt[r][q*4] = pF[(i0+r)*4 + q];
    float4 ev = eF[(j0+r)*4 + q];
    Es[q*4+0][r] = ev.x; Es[q*4+1][r] = ev.y;
    Es[q*4+2][r] = ev.z; Es[q*4+3][r] = ev.w;
  }
  __syncthreads();
  int tr = t >> 4, tc = t & 15;
  float acc[4][4];
  #pragma unroll
  for (int a = 0; a < 4; a++)
    #pragma unroll
    for (int k = 0; k < 4; k++) acc[a][k] = 0.f;
  #pragma unroll
  for (int d = 0; d < 16; d++){
    float4 eb = *(const float4*)&Es[d][tc*4];
    #pragma unroll
    for (int a = 0; a < 4; a++){
      float pa = Pt[tr*4+a][d];
      acc[a][0] += pa*eb.x; acc[a][1] += pa*eb.y;
      acc[a][2] += pa*eb.z; acc[a][3] += pa*eb.w;
    }
  }
  float bb = lp_b[0];
  #pragma unroll
  for (int a = 0; a < 4; a++)
    #pragma unroll
    for (int k = 0; k < 4; k++) acc[a][k] += bb;

  bool diag = (it == jt);
  float* ll = out + LL_OFF;

  // row-side tile max (mask j<=i on diag), reduce across the 16 tc-lanes
  #pragma unroll
  for (int a = 0; a < 4; a++){
    int R = tr*4 + a;
    float rm = -3.4e38f;
    #pragma unroll
    for (int k = 0; k < 4; k++){
      int C = tc*4 + k;
      float v = (diag && C <= R) ? -3.4e38f : acc[a][k];
      rm = fmaxf(rm, v);
    }
    #pragma unroll
    for (int m = 1; m < 16; m <<= 1)
      rm = fmaxf(rm, __shfl_xor_sync(0xffffffffu, rm, m));
    if (tc == 0){
      if (diag) rmx[R] = rm;
      else g_M1[(size_t)(i0+R)*128 + jt] = rm;
    }
  }

  // M/ll writes + masked ts staging
  #pragma unroll
  for (int a = 0; a < 4; a++){
    int i = i0 + tr*4 + a;
    int bi = i*(Nn-1) - (i*(i-1))/2 - i - 1;
    if (!diag){
      float4 w4 = make_float4(acc[a][0], acc[a][1], acc[a][2], acc[a][3]);
      *(float4*)&g_M[(size_t)i*Nn + j0 + tc*4] = w4;
      #pragma unroll
      for (int k = 0; k < 4; k++) ll[bi + j0 + tc*4 + k] = acc[a][k];
    } else {
      #pragma unroll
      for (int k = 0; k < 4; k++){
        int j = j0 + tc*4 + k;
        if (j > i){
          g_M[(size_t)i*Nn + j] = acc[a][k];
          ll[bi + j] = acc[a][k];
        } else if (j == i){
          g_M[(size_t)i*Nn + j] = -3.4e38f;
        }
      }
    }
    #pragma unroll
    for (int k = 0; k < 4; k++){
      int R = tr*4 + a, C = tc*4 + k;
      ts[R][C] = (diag && C <= R) ? -3.4e38f : acc[a][k];
    }
  }
  __syncthreads();
  // transposed M write (reads only C>R entries of ts; masking is invisible)
  #pragma unroll
  for (int a = 0; a < 4; a++){
    int jr = j0 + tr*4 + a;
    float w0 = ts[tc*4+0][tr*4+a];
    float w1 = ts[tc*4+1][tr*4+a];
    float w2 = ts[tc*4+2][tr*4+a];
    float w3 = ts[tc*4+3][tr*4+a];
    if (!diag){
      *(float4*)&g_M[(size_t)jr*Nn + i0 + tc*4] = make_float4(w0, w1, w2, w3);
    } else {
      float wv[4] = {w0, w1, w2, w3};
      #pragma unroll
      for (int k = 0; k < 4; k++){
        int ic = i0 + tc*4 + k;
        if (jr > ic) g_M[(size_t)jr*Nn + ic] = wv[k];
      }
    }
  }
  // column-side tile max from (masked) ts: rows j0+c get tile 'it'
  {
    int colc = t & 63, part = t >> 6;
    float cm = -3.4e38f;
    #pragma unroll
    for (int r = 0; r < 16; r++) cm = fmaxf(cm, ts[part*16 + r][colc]);
    cmx[part][colc] = cm;
  }
  __syncthreads();
  if (t < 64){
    float cmax = fmaxf(fmaxf(cmx[0][t], cmx[1][t]), fmaxf(cmx[2][t], cmx[3][t]));
    if (diag) g_M1[(size_t)(i0+t)*128 + it] = fmaxf(rmx[t], cmax);
    else      g_M1[(size_t)(j0+t)*128 + it] = cmax;
  }
}

// -------- top-7 per row via tile-max prefilter; warp per row --------
__global__ void __launch_bounds__(256) k_top2(){
  int row = (blockIdx.x*blockDim.x + threadIdx.x) >> 5;
  int lane = threadIdx.x & 31;
  float4 tm = *((const float4*)(g_M1 + (size_t)row*128) + lane);
  float tv[TOPK]; int tix[TOPK];
  #pragma unroll
  for (int s = 0; s < TOPK; s++){ tv[s] = -3.4e38f; tix[s] = 0x7fffffff; }
  ins7(tv, tix, tm.x, lane*4+0);
  ins7(tv, tix, tm.y, lane*4+1);
  ins7(tv, tix, tm.z, lane*4+2);
  ins7(tv, tix, tm.w, lane*4+3);
  // m7 = 7th largest tile max (safe screen threshold)
  float m7 = -3.4e38f;
  #pragma unroll 1
  for (int k = 0; k < TOPK; k++){
    float bv = tv[0]; int bi = tix[0];
    #pragma unroll
    for (int m = 16; m; m >>= 1){
      float ov = __shfl_xor_sync(0xffffffffu, bv, m);
      int   oi = __shfl_xor_sync(0xffffffffu, bi, m);
      if (ov > bv || (ov == bv && oi < bi)){ bv = ov; bi = oi; }
    }
    m7 = bv;
    if (tv[0] == bv && tix[0] == bi){
      #pragma unroll
      for (int s = 0; s < TOPK-1; s++){ tv[s] = tv[s+1]; tix[s] = tix[s+1]; }
      tv[TOPK-1] = -3.4e38f; tix[TOPK-1] = 0x7fffffff;
    }
  }
  unsigned bq[4];
  bq[0] = __ballot_sync(0xffffffffu, tm.x >= m7);
  bq[1] = __ballot_sync(0xffffffffu, tm.y >= m7);
  bq[2] = __ballot_sync(0xffffffffu, tm.z >= m7);
  bq[3] = __ballot_sync(0xffffffffu, tm.w >= m7);
  float tv2[TOPK]; int ti2[TOPK];
  #pragma unroll
  for (int s = 0; s < TOPK; s++){ tv2[s] = -3.4e38f; ti2[s] = 0x7fffffff; }
  const float* Mr = g_M + (size_t)row*Nn;
  #pragma unroll 1
  for (int q = 0; q < 4; q++){
    unsigned b = bq[q];
    while (b){
      int l = __ffs(b) - 1; b &= b - 1;
      int T = l*4 + q;
      int jj = T*64 + lane;
      float v0 = Mr[jj];
      float v1 = Mr[jj + 32];
      ins7(tv2, ti2, v0, jj);
      ins7(tv2, ti2, v1, jj + 32);
    }
  }
  wmerge7(tv2, ti2, lane, &g_sel[row*TOPK]);
}

// -------- edge build + dedup + edge_index output --------
__global__ void k_edges(float* __restrict__ out){
  int e = blockIdx.x*256 + threadIdx.x;
  if (e >= ET) return;
  int s, d, valid = 1;
  if (e < EK){
    int i = e / TOPK;
    int j = g_sel[e];
    if (j < i){
      #pragma unroll
      for (int kk = 0; kk < TOPK; kk++)
        if (g_sel[j*TOPK + kk] == i) valid = 0;
    }
    s = min(i, j); d = max(i, j);
  } else {
    s = d = e - EK;
  }
  g_src[e] = s; g_dst[e] = d; g_val[e] = valid;
  out[EI_OFF + e]      = (float)s;
  out[EI_OFF + ET + e] = (float)d;
}

// -------- feature GEMM: hlin = feat @ W  ([N,KD]x[KD,512]) --------
template<int KD, bool USE_GH>
__global__ void __launch_bounds__(128) k_feat(const float* __restrict__ xin,
                                              const float* __restrict__ W){
  __shared__ float fsT[KD][16];
  const float* feat = USE_GH ? g_h : xin;
  int r0 = blockIdx.x*16;
  int tid = threadIdx.x;
  for (int idx = tid; idx < 16*KD; idx += 128){
    int r = idx / KD, d = idx % KD;
    fsT[d][r] = feat[(r0+r)*KD + d];
  }
  __syncthreads();
  int c = blockIdx.y*128 + tid;
  float acc[16];
  #pragma unroll
  for (int r = 0; r < 16; r++) acc[r] = 0.f;
  for (int d = 0; d < KD; d++){
    float w = W[d*HF + c];
    const float4* fp = (const float4*)&fsT[d][0];
    float4 f0 = fp[0], f1 = fp[1], f2 = fp[2], f3 = fp[3];
    acc[0]  += f0.x*w; acc[1]  += f0.y*w; acc[2]  += f0.z*w; acc[3]  += f0.w*w;
    acc[4]  += f1.x*w; acc[5]  += f1.y*w; acc[6]  += f1.z*w; acc[7]  += f1.w*w;
    acc[8]  += f2.x*w; acc[9]  += f2.y*w; acc[10] += f2.z*w; acc[11] += f2.w*w;
    acc[12] += f3.x*w; acc[13] += f3.y*w; acc[14] += f3.z*w; acc[15] += f3.w*w;
  }
  #pragma unroll
  for (int r = 0; r < 16; r++) g_hlin[(size_t)(r0+r)*HF + c] = acc[r];
}

// -------- attention coefficients: asrc/adst[n,h] --------
__global__ void __launch_bounds__(128) k_attn(const float* __restrict__ as,
                                              const float* __restrict__ ad){
  int n = blockIdx.x;
  int h = threadIdx.x >> 5, l = threadIdx.x & 31;
  const float* hp = g_hlin + (size_t)n*HF + h*DHID;
  float s1 = 0.f, s2 = 0.f;
  #pragma unroll
  for (int t = 0; t < 4; t++){
    float v = hp[l + 32*t];
    s1 += v*as[h*DHID + l + 32*t];
    s2 += v*ad[h*DHID + l + 32*t];
  }
  for (int m = 16; m; m >>= 1){
    s1 += __shfl_xor_sync(0xffffffffu, s1, m);
    s2 += __shfl_xor_sync(0xffffffffu, s2, m);
  }
  if (!l){ g_asrc[n*NH + h] = s1; g_adst[n*NH + h] = s2; }
}

// -------- edge-parallel aggregation: warp per edge, vector red.v4 --------
__global__ void __launch_bounds__(256) k_agg(){
  int e = (blockIdx.x*256 + threadIdx.x) >> 5;
  int lane = threadIdx.x & 31;
  if (e >= ET || !__ldg(&g_val[e])) return;
  int s = __ldg(&g_src[e]), d = __ldg(&g_dst[e]);
  float w[NH];
  #pragma unroll
  for (int h = 0; h < NH; h++){
    float al = __ldg(&g_asrc[s*NH + h]) + __ldg(&g_adst[d*NH + h]);
    al = al > 0.f ? al : 0.2f*al;
    w[h] = expf(al);
  }
  if (lane < NH) atomicAdd(&g_den[d*NH + lane], w[lane]);
  const float4* hp = (const float4*)(g_hlin + (size_t)s*HF);
  float* ap = g_acc + (size_t)d*HF;
  #pragma unroll
  for (int t = 0; t < 4; t++){
    float4 hv = __ldg(&hp[lane + 32*t]);   // features t*128 + 4*lane .. +3 (head t)
    float ww = w[t];
    asm volatile("red.global.add.v4.f32 [%0], {%1, %2, %3, %4};"
      :: "l"(ap + t*128 + lane*4),
         "f"(hv.x*ww), "f"(hv.y*ww), "f"(hv.z*ww), "f"(hv.w*ww)
      : "memory");
  }
}

// -------- finalize: normalize, mean heads, bias+bn+elu --------
__global__ void __launch_bounds__(256) k_fin(const float* __restrict__ bias,
                                             const float* __restrict__ bng,
                                             const float* __restrict__ bnb){
  int n = blockIdx.x*2 + (threadIdx.x >> 7);
  int f = threadIdx.x & 127;
  float s = 0.f;
  #pragma unroll
  for (int h = 0; h < NH; h++)
    s += g_acc[(size_t)n*HF + h*DHID + f] / g_den[n*NH + h];
  float o = s*0.25f + bias[f];
  o = bng[f]*o*BNS + bnb[f];
  g_h[n*DHID + f] = eluf(o);
}

// -------- fused output heads: out0 = bn(h@f0+b), out1 = bn(elu(out0@f1+b)) --------
__global__ void __launch_bounds__(256) k_out(float* __restrict__ out,
    const float* __restrict__ f0w, const float* __restrict__ f0b,
    const float* __restrict__ bg0, const float* __restrict__ bb0,
    const float* __restrict__ f1w, const float* __restrict__ f1b,
    const float* __restrict__ bg1, const float* __restrict__ bb1){
  __shared__ float hs[32][DHID+1];
  __shared__ float o0[32][65];
  int r0 = blockIdx.x*32, tid = threadIdx.x;
  for (int idx = tid; idx < 32*DHID; idx += 256)
    hs[idx/DHID][idx%DHID] = g_h[r0*DHID + idx];
  __syncthreads();
  {
    int c = tid & 63, rg = tid >> 6;
    float acc[8];
    #pragma unroll
    for (int k = 0; k < 8; k++) acc[k] = 0.f;
    for (int d = 0; d < DHID; d++){
      float wv = f0w[d*64 + c];
      #pragma unroll
      for (int k = 0; k < 8; k++) acc[k] += hs[rg + 4*k][d]*wv;
    }
    float bv = f0b[c], gv = bg0[c], bbv = bb0[c];
    #pragma unroll
    for (int k = 0; k < 8; k++){
      float a = gv*(acc[k] + bv)*BNS + bbv;
      out[OUT0_OFF + (r0 + rg + 4*k)*64 + c] = a;
      o0[rg + 4*k][c] = a;
    }
  }
  __syncthreads();
  int rr = tid >> 4, cc = tid & 15;
  #pragma unroll
  for (int half = 0; half < 2; half++){
    int row = rr + 16*half;
    float a = f1b[cc];
    #pragma unroll 8
    for (int d = 0; d < 64; d++) a += o0[row][d]*f1w[d*DE + cc];
    a = eluf(a);
    a = bg1[cc]*a*BNS + bb1[cc];
    out[OUT1_OFF + (r0+row)*DE + cc] = a;
  }
}

extern "C" void kernel_launch(void* const* d_in, const int* in_sizes, int n_in,
                              void* d_out, int out_size) {
  const float* x      = (const float*)d_in[0];
  const float* il_w1  = (const float*)d_in[1];
  const float* il_b1  = (const float*)d_in[2];
  const float* il_g1  = (const float*)d_in[3];
  const float* il_be1 = (const float*)d_in[4];
  const float* il_w2  = (const float*)d_in[5];
  const float* il_b2  = (const float*)d_in[6];
  const float* il_g2  = (const float*)d_in[7];
  const float* il_be2 = (const float*)d_in[8];
  const float* lp_A   = (const float*)d_in[9];
  const float* lp_b   = (const float*)d_in[10];
  const float* g0_w   = (const float*)d_in[11];
  const float* g0_as  = (const float*)d_in[12];
  const float* g0_ad  = (const float*)d_in[13];
  const float* g0_b   = (const float*)d_in[14];
  const float* bn0_g  = (const float*)d_in[15];
  const float* bn0_b  = (const float*)d_in[16];
  const float* g1_w   = (const float*)d_in[17];
  const float* g1_as  = (const float*)d_in[18];
  const float* g1_ad  = (const float*)d_in[19];
  const float* g1_b   = (const float*)d_in[20];
  const float* bn1_g  = (const float*)d_in[21];
  const float* bn1_b  = (const float*)d_in[22];
  const float* f0_w   = (const float*)d_in[23];
  const float* f0_b   = (const float*)d_in[24];
  const float* fbn0_g = (const float*)d_in[25];
  const float* fbn0_b = (const float*)d_in[26];
  const float* f1_w   = (const float*)d_in[27];
  const float* f1_b   = (const float*)d_in[28];
  const float* fbn1_g = (const float*)d_in[29];
  const float* fbn1_b = (const float*)d_in[30];
  float* out = (float*)d_out;

  k_lin12<<<Nn/32, 256>>>(x, il_w1, il_b1, il_g1, il_be1,
                          il_w2, il_b2, il_g2, il_be2, lp_A);
  k_feat<DIN, false><<<dim3(Nn/16, HF/128), 128>>>(x, g0_w);
  k_zacc<<<(Nn*HF/4 + 255)/256, 256>>>();                       // layer-0 zero
  k_score<<<dim3(Nn/64, Nn/64), 256>>>(out, lp_b);              // ncu probe slot
  k_top2<<<Nn/8, 256>>>();
  k_edges<<<ET/256, 256>>>(out);
  // GAT layer 0
  k_attn<<<Nn, 128>>>(g0_as, g0_ad);
  k_agg<<<(ET*32)/256, 256>>>();
  k_fin<<<Nn/2, 256>>>(g0_b, bn0_g, bn0_b);
  // GAT layer 1
  k_feat<DHID, true><<<dim3(Nn/16, HF/128), 128>>>(x, g1_w);
  k_zacc<<<(Nn*HF/4 + 255)/256, 256>>>();
  k_attn<<<Nn, 128>>>(g1_as, g1_ad);
  k_agg<<<(ET*32)/256, 256>>>();
  k_fin<<<Nn/2, 256>>>(g1_b, bn1_g, bn1_b);
  // fused output heads
  k_out<<<Nn/32, 256>>>(out, f0_w, f0_b, fbn0_g, fbn0_b,
                        f1_w, f1_b, fbn1_g, fbn1_b);
}

// round 15
// speedup vs baseline: 1.0332x; 1.0332x over previous
#include <cuda_runtime.h>
#include <math.h>

#define Nn 8192
#define DIN 64
#define DHID 128
#define DE 16
#define NH 4
#define TOPK 7
#define EK (Nn*TOPK)
#define ET (EK+Nn)
#define HF (NH*DHID)
#define BNS 0.9999950000374997f

#define OUT0_OFF 0
#define OUT1_OFF (Nn*64)
#define EI_OFF (OUT1_OFF + Nn*16)
#define LL_OFF (EI_OFF + 2*ET)

// -------- device scratch (no allocs allowed) --------
__device__ float g_M[Nn*Nn];          // lower triangle only is written/read
__device__ float g_M1[Nn*128];        // per-row per-64col-tile maxes (4 MiB)
__device__ float g_emb[Nn*DE];
__device__ float g_P[Nn*DE];
__device__ int   g_sel[Nn*TOPK];
__device__ int   g_src[ET];
__device__ int   g_dst[ET];
__device__ int   g_val[ET];
__device__ float g_hlin[Nn*HF];
__device__ float g_asrc[Nn*NH];
__device__ float g_adst[Nn*NH];
__device__ float g_acc[Nn*HF];        // zeroed explicitly by k_zacc each layer
__device__ float g_den[Nn*NH];        // zeroed explicitly by k_zacc each layer
__device__ float g_h[Nn*DHID];

__device__ __forceinline__ float eluf(float x){ return x > 0.f ? x : expm1f(x); }

// sorted top-7 insert (descending value, ties -> lower index)
__device__ __forceinline__ void ins7(float (&tv)[TOPK], int (&tix)[TOPK], float v, int j){
  if (v > tv[TOPK-1] || (v == tv[TOPK-1] && j < tix[TOPK-1])){
    float cv = v; int ci = j;
    #pragma unroll
    for (int s = 0; s < TOPK; s++){
      bool bt = (cv > tv[s]) || (cv == tv[s] && ci < tix[s]);
      float nv = bt ? cv : tv[s]; int ni = bt ? ci : tix[s];
      cv = bt ? tv[s] : cv; ci = bt ? tix[s] : ci;
      tv[s] = nv; tix[s] = ni;
    }
  }
}

// warp-merge sorted per-lane lists -> global top-7 indices, write to selp
__device__ __forceinline__ void wmerge7(float (&tv)[TOPK], int (&tix)[TOPK],
                                        int lane, int* selp){
  #pragma unroll 1
  for (int k = 0; k < TOPK; k++){
    float bv = tv[0]; int bi = tix[0];
    #pragma unroll
    for (int m = 16; m; m >>= 1){
      float ov = __shfl_xor_sync(0xffffffffu, bv, m);
      int   oi = __shfl_xor_sync(0xffffffffu, bi, m);
      if (ov > bv || (ov == bv && oi < bi)){ bv = ov; bi = oi; }
    }
    if (lane == 0) selp[k] = bi;
    if (tv[0] == bv && tix[0] == bi){
      #pragma unroll
      for (int s = 0; s < TOPK-1; s++){ tv[s] = tv[s+1]; tix[s] = tix[s+1]; }
      tv[TOPK-1] = -3.4e38f; tix[TOPK-1] = 0x7fffffff;
    }
  }
}

// -------- zero accumulators (stateless per launch) --------
__global__ void __launch_bounds__(256) k_zacc(){
  int t = blockIdx.x*256 + threadIdx.x;
  float4* a4 = (float4*)g_acc;
  if (t < (Nn*HF)/4) a4[t] = make_float4(0.f, 0.f, 0.f, 0.f);
  if (t < Nn*NH) g_den[t] = 0.f;
}

// -------- fused initial MLP: x -> tmp128 -> emb, P  (32 rows/block) --------
__global__ void __launch_bounds__(256) k_lin12(const float* __restrict__ x,
    const float* __restrict__ w1, const float* __restrict__ b1,
    const float* __restrict__ g1, const float* __restrict__ be1,
    const float* __restrict__ w2, const float* __restrict__ b2,
    const float* __restrict__ g2, const float* __restrict__ be2,
    const float* __restrict__ lpA){
  __shared__ float xs[32][DIN+1];
  __shared__ float t128[32][DHID+1];
  __shared__ float es[32][DE+1];
  int r0 = blockIdx.x*32, tid = threadIdx.x;
  for (int idx = tid; idx < 32*DIN; idx += 256) xs[idx/DIN][idx%DIN] = x[r0*DIN + idx];
  __syncthreads();
  {
    int c = tid & 127, rg = tid >> 7;
    float acc[16];
    #pragma unroll
    for (int k = 0; k < 16; k++) acc[k] = 0.f;
    for (int d = 0; d < DIN; d++){
      float wv = w1[d*DHID + c];
      #pragma unroll
      for (int k = 0; k < 16; k++) acc[k] += xs[rg + 2*k][d]*wv;
    }
    float bv = b1[c], gv = g1[c], bev = be1[c];
    #pragma unroll
    for (int k = 0; k < 16; k++)
      t128[rg + 2*k][c] = eluf(gv*(acc[k] + bv)*BNS + bev);
  }
  __syncthreads();
  int rr = tid >> 4, cc = tid & 15;
  #pragma unroll
  for (int half = 0; half < 2; half++){
    int row = rr + 16*half;
    float a2 = b2[cc];
    #pragma unroll 8
    for (int d = 0; d < DHID; d++) a2 += t128[row][d]*w2[d*DE + cc];
    a2 = eluf(g2[cc]*a2*BNS + be2[cc]);
    es[row][cc] = a2;
    g_emb[(r0+row)*DE + cc] = a2;
  }
  __syncthreads();
  #pragma unroll
  for (int half = 0; half < 2; half++){
    int row = rr + 16*half;
    float p = 0.f;
    #pragma unroll
    for (int d = 0; d < DE; d++) p += es[row][d]*lpA[d*DE + cc];
    g_P[(r0+row)*DE + cc] = p;
  }
}

// -------- score tiles: upper-tri 64x64; write ll, M-lower, tile-maxes M1 --------
__global__ void __launch_bounds__(256) k_score(float* __restrict__ out,
                                               const float* __restrict__ lp_b){
  int jt = blockIdx.x, it = blockIdx.y;
  if (it > jt) return;
  __shared__ float Pt[64][16];
  __shared__ float Es[16][68];
  __shared__ float ts[64][68];
  __shared__ float rmx[64];
  __shared__ float cmx[4][64];
  int i0 = it*64, j0 = jt*64;
  int t = threadIdx.x;
  const float4* pF = (const float4*)g_P;
  const float4* eF = (const float4*)g_emb;
  {
    int r = t >> 2, q = t & 3;
    *(float4*)&Pt[r][q*4] = pF[(i0+r)*4 + q];
    float4 ev = eF[(j0+r)*4 + q];
    Es[q*4+0][r] = ev.x; Es[q*4+1][r] = ev.y;
    Es[q*4+2][r] = ev.z; Es[q*4+3][r] = ev.w;
  }
  __syncthreads();
  int tr = t >> 4, tc = t & 15;
  float acc[4][4];
  #pragma unroll
  for (int a = 0; a < 4; a++)
    #pragma unroll
    for (int k = 0; k < 4; k++) acc[a][k] = 0.f;
  #pragma unroll
  for (int d = 0; d < 16; d++){
    float4 eb = *(const float4*)&Es[d][tc*4];
    #pragma unroll
    for (int a = 0; a < 4; a++){
      float pa = Pt[tr*4+a][d];
      acc[a][0] += pa*eb.x; acc[a][1] += pa*eb.y;
      acc[a][2] += pa*eb.z; acc[a][3] += pa*eb.w;
    }
  }
  float bb = lp_b[0];
  #pragma unroll
  for (int a = 0; a < 4; a++)
    #pragma unroll
    for (int k = 0; k < 4; k++) acc[a][k] += bb;

  bool diag = (it == jt);
  float* ll = out + LL_OFF;

  // row-side tile max (mask j<=i on diag), reduce across the 16 tc-lanes
  #pragma unroll
  for (int a = 0; a < 4; a++){
    int R = tr*4 + a;
    float rm = -3.4e38f;
    #pragma unroll
    for (int k = 0; k < 4; k++){
      int C = tc*4 + k;
      float v = (diag && C <= R) ? -3.4e38f : acc[a][k];
      rm = fmaxf(rm, v);
    }
    #pragma unroll
    for (int m = 1; m < 16; m <<= 1)
      rm = fmaxf(rm, __shfl_xor_sync(0xffffffffu, rm, m));
    if (tc == 0){
      if (diag) rmx[R] = rm;
      else g_M1[(size_t)(i0+R)*128 + jt] = rm;
    }
  }

  // ll writes (upper triangle only) + masked ts staging
  #pragma unroll
  for (int a = 0; a < 4; a++){
    int i = i0 + tr*4 + a;
    int bi = i*(Nn-1) - (i*(i-1))/2 - i - 1;
    if (!diag){
      #pragma unroll
      for (int k = 0; k < 4; k++) ll[bi + j0 + tc*4 + k] = acc[a][k];
    } else {
      #pragma unroll
      for (int k = 0; k < 4; k++){
        int j = j0 + tc*4 + k;
        if (j > i) ll[bi + j] = acc[a][k];
      }
    }
    #pragma unroll
    for (int k = 0; k < 4; k++){
      int R = tr*4 + a, C = tc*4 + k;
      ts[R][C] = (diag && C <= R) ? -3.4e38f : acc[a][k];
    }
  }
  __syncthreads();
  // transposed M-lower write: rows jr > cols ic
  #pragma unroll
  for (int a = 0; a < 4; a++){
    int jr = j0 + tr*4 + a;
    float w0 = ts[tc*4+0][tr*4+a];
    float w1 = ts[tc*4+1][tr*4+a];
    float w2 = ts[tc*4+2][tr*4+a];
    float w3 = ts[tc*4+3][tr*4+a];
    if (!diag){
      *(float4*)&g_M[(size_t)jr*Nn + i0 + tc*4] = make_float4(w0, w1, w2, w3);
    } else {
      float wv[4] = {w0, w1, w2, w3};
      #pragma unroll
      for (int k = 0; k < 4; k++){
        int ic = i0 + tc*4 + k;
        if (jr > ic) g_M[(size_t)jr*Nn + ic] = wv[k];
      }
    }
  }
  // column-side tile max from (masked) ts: rows j0+c get tile 'it'
  {
    int colc = t & 63, part = t >> 6;
    float cm = -3.4e38f;
    #pragma unroll
    for (int r = 0; r < 16; r++) cm = fmaxf(cm, ts[part*16 + r][colc]);
    cmx[part][colc] = cm;
  }
  __syncthreads();
  if (t < 64){
    float cmax = fmaxf(fmaxf(cmx[0][t], cmx[1][t]), fmaxf(cmx[2][t], cmx[3][t]));
    if (diag) g_M1[(size_t)(i0+t)*128 + it] = fmaxf(rmx[t], cmax);
    else      g_M1[(size_t)(j0+t)*128 + it] = cmax;
  }
}

// -------- top-7 per row via tile-max prefilter; warp per row --------
// candidates: j<i from g_M lower (row-contiguous), j>i from ll (row-contiguous)
__global__ void __launch_bounds__(256) k_top2(const float* __restrict__ out){
  int row = (blockIdx.x*blockDim.x + threadIdx.x) >> 5;
  int lane = threadIdx.x & 31;
  float4 tm = *((const float4*)(g_M1 + (size_t)row*128) + lane);
  float tv[TOPK]; int tix[TOPK];
  #pragma unroll
  for (int s = 0; s < TOPK; s++){ tv[s] = -3.4e38f; tix[s] = 0x7fffffff; }
  ins7(tv, tix, tm.x, lane*4+0);
  ins7(tv, tix, tm.y, lane*4+1);
  ins7(tv, tix, tm.z, lane*4+2);
  ins7(tv, tix, tm.w, lane*4+3);
  // m7 = 7th largest tile max (safe screen threshold)
  float m7 = -3.4e38f;
  #pragma unroll 1
  for (int k = 0; k < TOPK; k++){
    float bv = tv[0]; int bi = tix[0];
    #pragma unroll
    for (int m = 16; m; m >>= 1){
      float ov = __shfl_xor_sync(0xffffffffu, bv, m);
      int   oi = __shfl_xor_sync(0xffffffffu, bi, m);
      if (ov > bv || (ov == bv && oi < bi)){ bv = ov; bi = oi; }
    }
    m7 = bv;
    if (tv[0] == bv && tix[0] == bi){
      #pragma unroll
      for (int s = 0; s < TOPK-1; s++){ tv[s] = tv[s+1]; tix[s] = tix[s+1]; }
      tv[TOPK-1] = -3.4e38f; tix[TOPK-1] = 0x7fffffff;
    }
  }
  unsigned bq[4];
  bq[0] = __ballot_sync(0xffffffffu, tm.x >= m7);
  bq[1] = __ballot_sync(0xffffffffu, tm.y >= m7);
  bq[2] = __ballot_sync(0xffffffffu, tm.z >= m7);
  bq[3] = __ballot_sync(0xffffffffu, tm.w >= m7);
  float tv2[TOPK]; int ti2[TOPK];
  #pragma unroll
  for (int s = 0; s < TOPK; s++){ tv2[s] = -3.4e38f; ti2[s] = 0x7fffffff; }
  const float* Mr = g_M + (size_t)row*Nn;
  const float* ll = out + LL_OFF;
  int bi = row*(Nn-1) - (row*(row-1))/2 - row - 1;
  #pragma unroll 1
  for (int q = 0; q < 4; q++){
    unsigned b = bq[q];
    while (b){
      int l = __ffs(b) - 1; b &= b - 1;
      int T = l*4 + q;
      int j1 = T*64 + lane;
      int j2 = j1 + 32;
      float v1 = (j1 < row) ? Mr[j1] : (j1 > row ? ll[bi + j1] : -3.4e38f);
      float v2 = (j2 < row) ? Mr[j2] : (j2 > row ? ll[bi + j2] : -3.4e38f);
      ins7(tv2, ti2, v1, j1);
      ins7(tv2, ti2, v2, j2);
    }
  }
  wmerge7(tv2, ti2, lane, &g_sel[row*TOPK]);
}

// -------- edge build + dedup + edge_index output --------
__global__ void k_edges(float* __restrict__ out){
  int e = blockIdx.x*256 + threadIdx.x;
  if (e >= ET) return;
  int s, d, valid = 1;
  if (e < EK){
    int i = e / TOPK;
    int j = g_sel[e];
    if (j < i){
      #pragma unroll
      for (int kk = 0; kk < TOPK; kk++)
        if (g_sel[j*TOPK + kk] == i) valid = 0;
    }
    s = min(i, j); d = max(i, j);
  } else {
    s = d = e - EK;
  }
  g_src[e] = s; g_dst[e] = d; g_val[e] = valid;
  out[EI_OFF + e]      = (float)s;
  out[EI_OFF + ET + e] = (float)d;
}

// -------- feature GEMM: hlin = feat @ W  ([N,KD]x[KD,512]) --------
template<int KD, bool USE_GH>
__global__ void __launch_bounds__(128) k_feat(const float* __restrict__ xin,
                                              const float* __restrict__ W){
  __shared__ float fsT[KD][16];
  const float* feat = USE_GH ? g_h : xin;
  int r0 = blockIdx.x*16;
  int tid = threadIdx.x;
  for (int idx = tid; idx < 16*KD; idx += 128){
    int r = idx / KD, d = idx % KD;
    fsT[d][r] = feat[(r0+r)*KD + d];
  }
  __syncthreads();
  int c = blockIdx.y*128 + tid;
  float acc[16];
  #pragma unroll
  for (int r = 0; r < 16; r++) acc[r] = 0.f;
  for (int d = 0; d < KD; d++){
    float w = W[d*HF + c];
    const float4* fp = (const float4*)&fsT[d][0];
    float4 f0 = fp[0], f1 = fp[1], f2 = fp[2], f3 = fp[3];
    acc[0]  += f0.x*w; acc[1]  += f0.y*w; acc[2]  += f0.z*w; acc[3]  += f0.w*w;
    acc[4]  += f1.x*w; acc[5]  += f1.y*w; acc[6]  += f1.z*w; acc[7]  += f1.w*w;
    acc[8]  += f2.x*w; acc[9]  += f2.y*w; acc[10] += f2.z*w; acc[11] += f2.w*w;
    acc[12] += f3.x*w; acc[13] += f3.y*w; acc[14] += f3.z*w; acc[15] += f3.w*w;
  }
  #pragma unroll
  for (int r = 0; r < 16; r++) g_hlin[(size_t)(r0+r)*HF + c] = acc[r];
}

// -------- attention coefficients: asrc/adst[n,h] --------
__global__ void __launch_bounds__(128) k_attn(const float* __restrict__ as,
                                              const float* __restrict__ ad){
  int n = blockIdx.x;
  int h = threadIdx.x >> 5, l = threadIdx.x & 31;
  const float* hp = g_hlin + (size_t)n*HF + h*DHID;
  float s1 = 0.f, s2 = 0.f;
  #pragma unroll
  for (int t = 0; t < 4; t++){
    float v = hp[l + 32*t];
    s1 += v*as[h*DHID + l + 32*t];
    s2 += v*ad[h*DHID + l + 32*t];
  }
  for (int m = 16; m; m >>= 1){
    s1 += __shfl_xor_sync(0xffffffffu, s1, m);
    s2 += __shfl_xor_sync(0xffffffffu, s2, m);
  }
  if (!l){ g_asrc[n*NH + h] = s1; g_adst[n*NH + h] = s2; }
}

// -------- edge-parallel aggregation: warp per edge, vector red.v4 --------
__global__ void __launch_bounds__(256) k_agg(){
  int e = (blockIdx.x*256 + threadIdx.x) >> 5;
  int lane = threadIdx.x & 31;
  if (e >= ET || !__ldg(&g_val[e])) return;
  int s = __ldg(&g_src[e]), d = __ldg(&g_dst[e]);
  float w[NH];
  #pragma unroll
  for (int h = 0; h < NH; h++){
    float al = __ldg(&g_asrc[s*NH + h]) + __ldg(&g_adst[d*NH + h]);
    al = al > 0.f ? al : 0.2f*al;
    w[h] = expf(al);
  }
  if (lane < NH) atomicAdd(&g_den[d*NH + lane], w[lane]);
  const float4* hp = (const float4*)(g_hlin + (size_t)s*HF);
  float* ap = g_acc + (size_t)d*HF;
  #pragma unroll
  for (int t = 0; t < 4; t++){
    float4 hv = __ldg(&hp[lane + 32*t]);
    float ww = w[t];
    asm volatile("red.global.add.v4.f32 [%0], {%1, %2, %3, %4};"
      :: "l"(ap + t*128 + lane*4),
         "f"(hv.x*ww), "f"(hv.y*ww), "f"(hv.z*ww), "f"(hv.w*ww)
      : "memory");
  }
}

// -------- finalize: normalize, mean heads, bias+bn+elu --------
__global__ void __launch_bounds__(256) k_fin(const float* __restrict__ bias,
                                             const float* __restrict__ bng,
                                             const float* __restrict__ bnb){
  int n = blockIdx.x*2 + (threadIdx.x >> 7);
  int f = threadIdx.x & 127;
  float s = 0.f;
  #pragma unroll
  for (int h = 0; h < NH; h++)
    s += g_acc[(size_t)n*HF + h*DHID + f] / g_den[n*NH + h];
  float o = s*0.25f + bias[f];
  o = bng[f]*o*BNS + bnb[f];
  g_h[n*DHID + f] = eluf(o);
}

// -------- fused output heads: out0 = bn(h@f0+b), out1 = bn(elu(out0@f1+b)) --------
__global__ void __launch_bounds__(256) k_out(float* __restrict__ out,
    const float* __restrict__ f0w, const float* __restrict__ f0b,
    const float* __restrict__ bg0, const float* __restrict__ bb0,
    const float* __restrict__ f1w, const float* __restrict__ f1b,
    const float* __restrict__ bg1, const float* __restrict__ bb1){
  __shared__ float hs[32][DHID+1];
  __shared__ float o0[32][65];
  int r0 = blockIdx.x*32, tid = threadIdx.x;
  for (int idx = tid; idx < 32*DHID; idx += 256)
    hs[idx/DHID][idx%DHID] = g_h[r0*DHID + idx];
  __syncthreads();
  {
    int c = tid & 63, rg = tid >> 6;
    float acc[8];
    #pragma unroll
    for (int k = 0; k < 8; k++) acc[k] = 0.f;
    for (int d = 0; d < DHID; d++){
      float wv = f0w[d*64 + c];
      #pragma unroll
      for (int k = 0; k < 8; k++) acc[k] += hs[rg + 4*k][d]*wv;
    }
    float bv = f0b[c], gv = bg0[c], bbv = bb0[c];
    #pragma unroll
    for (int k = 0; k < 8; k++){
      float a = gv*(acc[k] + bv)*BNS + bbv;
      out[OUT0_OFF + (r0 + rg + 4*k)*64 + c] = a;
      o0[rg + 4*k][c] = a;
    }
  }
  __syncthreads();
  int rr = tid >> 4, cc = tid & 15;
  #pragma unroll
  for (int half = 0; half < 2; half++){
    int row = rr + 16*half;
    float a = f1b[cc];
    #pragma unroll 8
    for (int d = 0; d < 64; d++) a += o0[row][d]*f1w[d*DE + cc];
    a = eluf(a);
    a = bg1[cc]*a*BNS + bb1[cc];
    out[OUT1_OFF + (r0+row)*DE + cc] = a;
  }
}

extern "C" void kernel_launch(void* const* d_in, const int* in_sizes, int n_in,
                              void* d_out, int out_size) {
  const float* x      = (const float*)d_in[0];
  const float* il_w1  = (const float*)d_in[1];
  const float* il_b1  = (const float*)d_in[2];
  const float* il_g1  = (const float*)d_in[3];
  const float* il_be1 = (const float*)d_in[4];
  const float* il_w2  = (const float*)d_in[5];
  const float* il_b2  = (const float*)d_in[6];
  const float* il_g2  = (const float*)d_in[7];
  const float* il_be2 = (const float*)d_in[8];
  const float* lp_A   = (const float*)d_in[9];
  const float* lp_b   = (const float*)d_in[10];
  const float* g0_w   = (const float*)d_in[11];
  const float* g0_as  = (const float*)d_in[12];
  const float* g0_ad  = (const float*)d_in[13];
  const float* g0_b   = (const float*)d_in[14];
  const float* bn0_g  = (const float*)d_in[15];
  const float* bn0_b  = (const float*)d_in[16];
  const float* g1_w   = (const float*)d_in[17];
  const float* g1_as  = (const float*)d_in[18];
  const float* g1_ad  = (const float*)d_in[19];
  const float* g1_b   = (const float*)d_in[20];
  const float* bn1_g  = (const float*)d_in[21];
  const float* bn1_b  = (const float*)d_in[22];
  const float* f0_w   = (const float*)d_in[23];
  const float* f0_b   = (const float*)d_in[24];
  const float* fbn0_g = (const float*)d_in[25];
  const float* fbn0_b = (const float*)d_in[26];
  const float* f1_w   = (const float*)d_in[27];
  const float* f1_b   = (const float*)d_in[28];
  const float* fbn1_g = (const float*)d_in[29];
  const float* fbn1_b = (const float*)d_in[30];
  float* out = (float*)d_out;

  k_lin12<<<Nn/32, 256>>>(x, il_w1, il_b1, il_g1, il_be1,
                          il_w2, il_b2, il_g2, il_be2, lp_A);
  k_feat<DIN, false><<<dim3(Nn/16, HF/128), 128>>>(x, g0_w);
  k_zacc<<<(Nn*HF/4 + 255)/256, 256>>>();                       // layer-0 zero
  k_score<<<dim3(Nn/64, Nn/64), 256>>>(out, lp_b);              // ncu probe slot
  k_top2<<<Nn/8, 256>>>(out);
  k_edges<<<ET/256, 256>>>(out);
  // GAT layer 0
  k_attn<<<Nn, 128>>>(g0_as, g0_ad);
  k_agg<<<(ET*32)/256, 256>>>();
  k_fin<<<Nn/2, 256>>>(g0_b, bn0_g, bn0_b);
  // GAT layer 1
  k_feat<DHID, true><<<dim3(Nn/16, HF/128), 128>>>(x, g1_w);
  k_zacc<<<(Nn*HF/4 + 255)/256, 256>>>();
  k_attn<<<Nn, 128>>>(g1_as, g1_ad);
  k_agg<<<(ET*32)/256, 256>>>();
  k_fin<<<Nn/2, 256>>>(g1_b, bn1_g, bn1_b);
  // fused output heads
  k_out<<<Nn/32, 256>>>(out, f0_w, f0_b, fbn0_g, fbn0_b,
                        f1_w, f1_b, fbn1_g, fbn1_b);
}

// round 16
// speedup vs baseline: 1.0450x; 1.0114x over previous
#include <cuda_runtime.h>
#include <math.h>

#define Nn 8192
#define DIN 64
#define DHID 128
#define DE 16
#define NH 4
#define TOPK 7
#define EK (Nn*TOPK)
#define ET (EK+Nn)
#define HF (NH*DHID)
#define BNS 0.9999950000374997f

#define OUT0_OFF 0
#define OUT1_OFF (Nn*64)
#define EI_OFF (OUT1_OFF + Nn*16)
#define LL_OFF (EI_OFF + 2*ET)

// -------- device scratch (no allocs allowed) --------
__device__ float g_M[Nn*Nn];          // lower triangle only is written/read
__device__ float g_M1[Nn*128];        // per-row per-64col-tile maxes (4 MiB)
__device__ float g_emb[Nn*DE];
__device__ float g_P[Nn*DE];
__device__ int   g_sel[Nn*TOPK];
__device__ int   g_src[ET];
__device__ int   g_dst[ET];
__device__ int   g_val[ET];
__device__ float g_hlin[Nn*HF];
__device__ float g_asrc[Nn*NH];
__device__ float g_adst[Nn*NH];
__device__ float g_acc[Nn*HF];        // zeroed by k_zacc (launch start) + k_fin self-clean
__device__ float g_den[Nn*NH];
__device__ float g_h[Nn*DHID];

__device__ __forceinline__ float eluf(float x){ return x > 0.f ? x : expm1f(x); }

// sorted top-7 insert (descending value, ties -> lower index)
__device__ __forceinline__ void ins7(float (&tv)[TOPK], int (&tix)[TOPK], float v, int j){
  if (v > tv[TOPK-1] || (v == tv[TOPK-1] && j < tix[TOPK-1])){
    float cv = v; int ci = j;
    #pragma unroll
    for (int s = 0; s < TOPK; s++){
      bool bt = (cv > tv[s]) || (cv == tv[s] && ci < tix[s]);
      float nv = bt ? cv : tv[s]; int ni = bt ? ci : tix[s];
      cv = bt ? tv[s] : cv; ci = bt ? tix[s] : ci;
      tv[s] = nv; tix[s] = ni;
    }
  }
}

// warp-merge sorted per-lane lists -> global top-7 indices, write to selp
__device__ __forceinline__ void wmerge7(float (&tv)[TOPK], int (&tix)[TOPK],
                                        int lane, int* selp){
  #pragma unroll 1
  for (int k = 0; k < TOPK; k++){
    float bv = tv[0]; int bi = tix[0];
    #pragma unroll
    for (int m = 16; m; m >>= 1){
      float ov = __shfl_xor_sync(0xffffffffu, bv, m);
      int   oi = __shfl_xor_sync(0xffffffffu, bi, m);
      if (ov > bv || (ov == bv && oi < bi)){ bv = ov; bi = oi; }
    }
    if (lane == 0) selp[k] = bi;
    if (tv[0] == bv && tix[0] == bi){
      #pragma unroll
      for (int s = 0; s < TOPK-1; s++){ tv[s] = tv[s+1]; tix[s] = tix[s+1]; }
      tv[TOPK-1] = -3.4e38f; tix[TOPK-1] = 0x7fffffff;
    }
  }
}

// -------- zero accumulators (start of every replay -> stateless) --------
__global__ void __launch_bounds__(256) k_zacc(){
  int t = blockIdx.x*256 + threadIdx.x;
  float4* a4 = (float4*)g_acc;
  if (t < (Nn*HF)/4) a4[t] = make_float4(0.f, 0.f, 0.f, 0.f);
  if (t < Nn*NH) g_den[t] = 0.f;
}

// -------- fused initial MLP: x -> tmp128 -> emb, P  (32 rows/block) --------
__global__ void __launch_bounds__(256) k_lin12(const float* __restrict__ x,
    const float* __restrict__ w1, const float* __restrict__ b1,
    const float* __restrict__ g1, const float* __restrict__ be1,
    const float* __restrict__ w2, const float* __restrict__ b2,
    const float* __restrict__ g2, const float* __restrict__ be2,
    const float* __restrict__ lpA){
  __shared__ float xs[32][DIN+1];
  __shared__ float t128[32][DHID+1];
  __shared__ float es[32][DE+1];
  int r0 = blockIdx.x*32, tid = threadIdx.x;
  for (int idx = tid; idx < 32*DIN; idx += 256) xs[idx/DIN][idx%DIN] = x[r0*DIN + idx];
  __syncthreads();
  {
    int c = tid & 127, rg = tid >> 7;
    float acc[16];
    #pragma unroll
    for (int k = 0; k < 16; k++) acc[k] = 0.f;
    for (int d = 0; d < DIN; d++){
      float wv = w1[d*DHID + c];
      #pragma unroll
      for (int k = 0; k < 16; k++) acc[k] += xs[rg + 2*k][d]*wv;
    }
    float bv = b1[c], gv = g1[c], bev = be1[c];
    #pragma unroll
    for (int k = 0; k < 16; k++)
      t128[rg + 2*k][c] = eluf(gv*(acc[k] + bv)*BNS + bev);
  }
  __syncthreads();
  int rr = tid >> 4, cc = tid & 15;
  #pragma unroll
  for (int half = 0; half < 2; half++){
    int row = rr + 16*half;
    float a2 = b2[cc];
    #pragma unroll 8
    for (int d = 0; d < DHID; d++) a2 += t128[row][d]*w2[d*DE + cc];
    a2 = eluf(g2[cc]*a2*BNS + be2[cc]);
    es[row][cc] = a2;
    g_emb[(r0+row)*DE + cc] = a2;
  }
  __syncthreads();
  #pragma unroll
  for (int half = 0; half < 2; half++){
    int row = rr + 16*half;
    float p = 0.f;
    #pragma unroll
    for (int d = 0; d < DE; d++) p += es[row][d]*lpA[d*DE + cc];
    g_P[(r0+row)*DE + cc] = p;
  }
}

// -------- score tiles: upper-tri 64x64; write ll, M-lower, tile-maxes M1 --------
__global__ void __launch_bounds__(256) k_score(float* __restrict__ out,
                                               const float* __restrict__ lp_b){
  int jt = blockIdx.x, it = blockIdx.y;
  if (it > jt) return;
  __shared__ float Pt[64][16];
  __shared__ float Es[16][68];
  __shared__ float ts[64][68];
  __shared__ float rmx[64];
  __shared__ float cmx[4][64];
  int i0 = it*64, j0 = jt*64;
  int t = threadIdx.x;
  const float4* pF = (const float4*)g_P;
  const float4* eF = (const float4*)g_emb;
  {
    int r = t >> 2, q = t & 3;
    *(float4*)&Pt[r][q*4] = pF[(i0+r)*4 + q];
    float4 ev = eF[(j0+r)*4 + q];
    Es[q*4+0][r] = ev.x; Es[q*4+1][r] = ev.y;
    Es[q*4+2][r] = ev.z; Es[q*4+3][r] = ev.w;
  }
  __syncthreads();
  int tr = t >> 4, tc = t & 15;
  float acc[4][4];
  #pragma unroll
  for (int a = 0; a < 4; a++)
    #pragma unroll
    for (int k = 0; k < 4; k++) acc[a][k] = 0.f;
  // d-loop in groups of 4: Pt fetched as float4 (rows 64B-aligned)
  #pragma unroll
  for (int dg = 0; dg < 4; dg++){
    float4 e0 = *(const float4*)&Es[dg*4+0][tc*4];
    float4 e1 = *(const float4*)&Es[dg*4+1][tc*4];
    float4 e2 = *(const float4*)&Es[dg*4+2][tc*4];
    float4 e3 = *(const float4*)&Es[dg*4+3][tc*4];
    #pragma unroll
    for (int a = 0; a < 4; a++){
      float4 p = *(const float4*)&Pt[tr*4+a][dg*4];
      acc[a][0] += p.x*e0.x + p.y*e1.x + p.z*e2.x + p.w*e3.x;
      acc[a][1] += p.x*e0.y + p.y*e1.y + p.z*e2.y + p.w*e3.y;
      acc[a][2] += p.x*e0.z + p.y*e1.z + p.z*e2.z + p.w*e3.z;
      acc[a][3] += p.x*e0.w + p.y*e1.w + p.z*e2.w + p.w*e3.w;
    }
  }
  float bb = lp_b[0];
  #pragma unroll
  for (int a = 0; a < 4; a++)
    #pragma unroll
    for (int k = 0; k < 4; k++) acc[a][k] += bb;

  bool diag = (it == jt);
  float* ll = out + LL_OFF;

  // row-side tile max (mask j<=i on diag), reduce across the 16 tc-lanes
  #pragma unroll
  for (int a = 0; a < 4; a++){
    int R = tr*4 + a;
    float rm = -3.4e38f;
    #pragma unroll
    for (int k = 0; k < 4; k++){
      int C = tc*4 + k;
      float v = (diag && C <= R) ? -3.4e38f : acc[a][k];
      rm = fmaxf(rm, v);
    }
    #pragma unroll
    for (int m = 1; m < 16; m <<= 1)
      rm = fmaxf(rm, __shfl_xor_sync(0xffffffffu, rm, m));
    if (tc == 0){
      if (diag) rmx[R] = rm;
      else g_M1[(size_t)(i0+R)*128 + jt] = rm;
    }
  }

  // ll writes (upper triangle only) + masked ts staging
  #pragma unroll
  for (int a = 0; a < 4; a++){
    int i = i0 + tr*4 + a;
    int bi = i*(Nn-1) - (i*(i-1))/2 - i - 1;
    if (!diag){
      #pragma unroll
      for (int k = 0; k < 4; k++) ll[bi + j0 + tc*4 + k] = acc[a][k];
    } else {
      #pragma unroll
      for (int k = 0; k < 4; k++){
        int j = j0 + tc*4 + k;
        if (j > i) ll[bi + j] = acc[a][k];
      }
    }
    #pragma unroll
    for (int k = 0; k < 4; k++){
      int R = tr*4 + a, C = tc*4 + k;
      ts[R][C] = (diag && C <= R) ? -3.4e38f : acc[a][k];
    }
  }
  __syncthreads();
  // transposed M-lower write: rows jr > cols ic
  #pragma unroll
  for (int a = 0; a < 4; a++){
    int jr = j0 + tr*4 + a;
    float w0 = ts[tc*4+0][tr*4+a];
    float w1 = ts[tc*4+1][tr*4+a];
    float w2 = ts[tc*4+2][tr*4+a];
    float w3 = ts[tc*4+3][tr*4+a];
    if (!diag){
      *(float4*)&g_M[(size_t)jr*Nn + i0 + tc*4] = make_float4(w0, w1, w2, w3);
    } else {
      float wv[4] = {w0, w1, w2, w3};
      #pragma unroll
      for (int k = 0; k < 4; k++){
        int ic = i0 + tc*4 + k;
        if (jr > ic) g_M[(size_t)jr*Nn + ic] = wv[k];
      }
    }
  }
  // column-side tile max from (masked) ts: rows j0+c get tile 'it'
  {
    int colc = t & 63, part = t >> 6;
    float cm = -3.4e38f;
    #pragma unroll
    for (int r = 0; r < 16; r++) cm = fmaxf(cm, ts[part*16 + r][colc]);
    cmx[part][colc] = cm;
  }
  __syncthreads();
  if (t < 64){
    float cmax = fmaxf(fmaxf(cmx[0][t], cmx[1][t]), fmaxf(cmx[2][t], cmx[3][t]));
    if (diag) g_M1[(size_t)(i0+t)*128 + it] = fmaxf(rmx[t], cmax);
    else      g_M1[(size_t)(j0+t)*128 + it] = cmax;
  }
}

// -------- top-7 per row via tile-max prefilter; warp per row --------
__global__ void __launch_bounds__(256) k_top2(const float* __restrict__ out){
  int row = (blockIdx.x*blockDim.x + threadIdx.x) >> 5;
  int lane = threadIdx.x & 31;
  float4 tm = *((const float4*)(g_M1 + (size_t)row*128) + lane);
  float tv[TOPK]; int tix[TOPK];
  #pragma unroll
  for (int s = 0; s < TOPK; s++){ tv[s] = -3.4e38f; tix[s] = 0x7fffffff; }
  ins7(tv, tix, tm.x, lane*4+0);
  ins7(tv, tix, tm.y, lane*4+1);
  ins7(tv, tix, tm.z, lane*4+2);
  ins7(tv, tix, tm.w, lane*4+3);
  float m7 = -3.4e38f;
  #pragma unroll 1
  for (int k = 0; k < TOPK; k++){
    float bv = tv[0]; int bi = tix[0];
    #pragma unroll
    for (int m = 16; m; m >>= 1){
      float ov = __shfl_xor_sync(0xffffffffu, bv, m);
      int   oi = __shfl_xor_sync(0xffffffffu, bi, m);
      if (ov > bv || (ov == bv && oi < bi)){ bv = ov; bi = oi; }
    }
    m7 = bv;
    if (tv[0] == bv && tix[0] == bi){
      #pragma unroll
      for (int s = 0; s < TOPK-1; s++){ tv[s] = tv[s+1]; tix[s] = tix[s+1]; }
      tv[TOPK-1] = -3.4e38f; tix[TOPK-1] = 0x7fffffff;
    }
  }
  unsigned bq[4];
  bq[0] = __ballot_sync(0xffffffffu, tm.x >= m7);
  bq[1] = __ballot_sync(0xffffffffu, tm.y >= m7);
  bq[2] = __ballot_sync(0xffffffffu, tm.z >= m7);
  bq[3] = __ballot_sync(0xffffffffu, tm.w >= m7);
  float tv2[TOPK]; int ti2[TOPK];
  #pragma unroll
  for (int s = 0; s < TOPK; s++){ tv2[s] = -3.4e38f; ti2[s] = 0x7fffffff; }
  const float* Mr = g_M + (size_t)row*Nn;
  const float* ll = out + LL_OFF;
  int bi = row*(Nn-1) - (row*(row-1))/2 - row - 1;
  #pragma unroll 1
  for (int q = 0; q < 4; q++){
    unsigned b = bq[q];
    while (b){
      int l = __ffs(b) - 1; b &= b - 1;
      int T = l*4 + q;
      int j1 = T*64 + lane;
      int j2 = j1 + 32;
      float v1 = (j1 < row) ? Mr[j1] : (j1 > row ? ll[bi + j1] : -3.4e38f);
      float v2 = (j2 < row) ? Mr[j2] : (j2 > row ? ll[bi + j2] : -3.4e38f);
      ins7(tv2, ti2, v1, j1);
      ins7(tv2, ti2, v2, j2);
    }
  }
  wmerge7(tv2, ti2, lane, &g_sel[row*TOPK]);
}

// -------- edge build + dedup + edge_index output --------
__global__ void k_edges(float* __restrict__ out){
  int e = blockIdx.x*256 + threadIdx.x;
  if (e >= ET) return;
  int s, d, valid = 1;
  if (e < EK){
    int i = e / TOPK;
    int j = g_sel[e];
    if (j < i){
      #pragma unroll
      for (int kk = 0; kk < TOPK; kk++)
        if (g_sel[j*TOPK + kk] == i) valid = 0;
    }
    s = min(i, j); d = max(i, j);
  } else {
    s = d = e - EK;
  }
  g_src[e] = s; g_dst[e] = d; g_val[e] = valid;
  out[EI_OFF + e]      = (float)s;
  out[EI_OFF + ET + e] = (float)d;
}

// -------- feature GEMM + fused attention dots --------
// block (x,y): rows [16x, 16x+16), cols = head y's 128 features. Since one block
// covers a full head for its rows, asrc/adst are complete dots -> plain stores.
template<int KD, bool USE_GH>
__global__ void __launch_bounds__(128) k_feat(const float* __restrict__ xin,
                                              const float* __restrict__ W,
                                              const float* __restrict__ as,
                                              const float* __restrict__ ad){
  __shared__ float fsT[KD][16];
  __shared__ float red1[16][4];
  __shared__ float red2[16][4];
  const float* feat = USE_GH ? g_h : xin;
  int r0 = blockIdx.x*16;
  int tid = threadIdx.x;
  int h = blockIdx.y;
  for (int idx = tid; idx < 16*KD; idx += 128){
    int r = idx / KD, d = idx % KD;
    fsT[d][r] = feat[(r0+r)*KD + d];
  }
  __syncthreads();
  int c = h*128 + tid;
  float acc[16];
  #pragma unroll
  for (int r = 0; r < 16; r++) acc[r] = 0.f;
  for (int d = 0; d < KD; d++){
    float w = W[d*HF + c];
    const float4* fp = (const float4*)&fsT[d][0];
    float4 f0 = fp[0], f1 = fp[1], f2 = fp[2], f3 = fp[3];
    acc[0]  += f0.x*w; acc[1]  += f0.y*w; acc[2]  += f0.z*w; acc[3]  += f0.w*w;
    acc[4]  += f1.x*w; acc[5]  += f1.y*w; acc[6]  += f1.z*w; acc[7]  += f1.w*w;
    acc[8]  += f2.x*w; acc[9]  += f2.y*w; acc[10] += f2.z*w; acc[11] += f2.w*w;
    acc[12] += f3.x*w; acc[13] += f3.y*w; acc[14] += f3.z*w; acc[15] += f3.w*w;
  }
  #pragma unroll
  for (int r = 0; r < 16; r++) g_hlin[(size_t)(r0+r)*HF + c] = acc[r];
  // fused attention coefficients
  float asv = as[h*DHID + tid];
  float adv = ad[h*DHID + tid];
  int warp = tid >> 5, lane = tid & 31;
  #pragma unroll
  for (int r = 0; r < 16; r++){
    float p1 = acc[r]*asv, p2 = acc[r]*adv;
    #pragma unroll
    for (int m = 16; m; m >>= 1){
      p1 += __shfl_xor_sync(0xffffffffu, p1, m);
      p2 += __shfl_xor_sync(0xffffffffu, p2, m);
    }
    if (lane == 0){ red1[r][warp] = p1; red2[r][warp] = p2; }
  }
  __syncthreads();
  if (tid < 16){
    g_asrc[(r0+tid)*NH + h] = red1[tid][0]+red1[tid][1]+red1[tid][2]+red1[tid][3];
  } else if (tid < 32){
    int r = tid - 16;
    g_adst[(r0+r)*NH + h] = red2[r][0]+red2[r][1]+red2[r][2]+red2[r][3];
  }
}

// -------- edge-parallel aggregation: warp per edge, vector red.v4 --------
__global__ void __launch_bounds__(256) k_agg(){
  int e = (blockIdx.x*256 + threadIdx.x) >> 5;
  int lane = threadIdx.x & 31;
  if (e >= ET || !__ldg(&g_val[e])) return;
  int s = __ldg(&g_src[e]), d = __ldg(&g_dst[e]);
  float w[NH];
  #pragma unroll
  for (int h = 0; h < NH; h++){
    float al = __ldg(&g_asrc[s*NH + h]) + __ldg(&g_adst[d*NH + h]);
    al = al > 0.f ? al : 0.2f*al;
    w[h] = expf(al);
  }
  if (lane < NH) atomicAdd(&g_den[d*NH + lane], w[lane]);
  const float4* hp = (const float4*)(g_hlin + (size_t)s*HF);
  float* ap = g_acc + (size_t)d*HF;
  #pragma unroll
  for (int t = 0; t < 4; t++){
    float4 hv = __ldg(&hp[lane + 32*t]);
    float ww = w[t];
    asm volatile("red.global.add.v4.f32 [%0], {%1, %2, %3, %4};"
      :: "l"(ap + t*128 + lane*4),
         "f"(hv.x*ww), "f"(hv.y*ww), "f"(hv.z*ww), "f"(hv.w*ww)
      : "memory");
  }
}

// -------- finalize + self-clean acc/den (covered by replay-start k_zacc) --------
__global__ void __launch_bounds__(256) k_fin(const float* __restrict__ bias,
                                             const float* __restrict__ bng,
                                             const float* __restrict__ bnb){
  int n = blockIdx.x*2 + (threadIdx.x >> 7);
  int f = threadIdx.x & 127;
  float s = 0.f;
  #pragma unroll
  for (int h = 0; h < NH; h++)
    s += g_acc[(size_t)n*HF + h*DHID + f] / g_den[n*NH + h];
  float o = s*0.25f + bias[f];
  o = bng[f]*o*BNS + bnb[f];
  g_h[n*DHID + f] = eluf(o);
  // self-clean: each thread zeroes exactly the acc slots it alone read
  #pragma unroll
  for (int h = 0; h < NH; h++) g_acc[(size_t)n*HF + h*DHID + f] = 0.f;
  __syncthreads();     // all den reads complete
  if (f < NH) g_den[n*NH + f] = 0.f;
}

// -------- fused output heads: out0 = bn(h@f0+b), out1 = bn(elu(out0@f1+b)) --------
__global__ void __launch_bounds__(256) k_out(float* __restrict__ out,
    const float* __restrict__ f0w, const float* __restrict__ f0b,
    const float* __restrict__ bg0, const float* __restrict__ bb0,
    const float* __restrict__ f1w, const float* __restrict__ f1b,
    const float* __restrict__ bg1, const float* __restrict__ bb1){
  __shared__ float hs[32][DHID+1];
  __shared__ float o0[32][65];
  int r0 = blockIdx.x*32, tid = threadIdx.x;
  for (int idx = tid; idx < 32*DHID; idx += 256)
    hs[idx/DHID][idx%DHID] = g_h[r0*DHID + idx];
  __syncthreads();
  {
    int c = tid & 63, rg = tid >> 6;
    float acc[8];
    #pragma unroll
    for (int k = 0; k < 8; k++) acc[k] = 0.f;
    for (int d = 0; d < DHID; d++){
      float wv = f0w[d*64 + c];
      #pragma unroll
      for (int k = 0; k < 8; k++) acc[k] += hs[rg + 4*k][d]*wv;
    }
    float bv = f0b[c], gv = bg0[c], bbv = bb0[c];
    #pragma unroll
    for (int k = 0; k < 8; k++){
      float a = gv*(acc[k] + bv)*BNS + bbv;
      out[OUT0_OFF + (r0 + rg + 4*k)*64 + c] = a;
      o0[rg + 4*k][c] = a;
    }
  }
  __syncthreads();
  int rr = tid >> 4, cc = tid & 15;
  #pragma unroll
  for (int half = 0; half < 2; half++){
    int row = rr + 16*half;
    float a = f1b[cc];
    #pragma unroll 8
    for (int d = 0; d < 64; d++) a += o0[row][d]*f1w[d*DE + cc];
    a = eluf(a);
    a = bg1[cc]*a*BNS + bb1[cc];
    out[OUT1_OFF + (r0+row)*DE + cc] = a;
  }
}

extern "C" void kernel_launch(void* const* d_in, const int* in_sizes, int n_in,
                              void* d_out, int out_size) {
  const float* x      = (const float*)d_in[0];
  const float* il_w1  = (const float*)d_in[1];
  const float* il_b1  = (const float*)d_in[2];
  const float* il_g1  = (const float*)d_in[3];
  const float* il_be1 = (const float*)d_in[4];
  const float* il_w2  = (const float*)d_in[5];
  const float* il_b2  = (const float*)d_in[6];
  const float* il_g2  = (const float*)d_in[7];
  const float* il_be2 = (const float*)d_in[8];
  const float* lp_A   = (const float*)d_in[9];
  const float* lp_b   = (const float*)d_in[10];
  const float* g0_w   = (const float*)d_in[11];
  const float* g0_as  = (const float*)d_in[12];
  const float* g0_ad  = (const float*)d_in[13];
  const float* g0_b   = (const float*)d_in[14];
  const float* bn0_g  = (const float*)d_in[15];
  const float* bn0_b  = (const float*)d_in[16];
  const float* g1_w   = (const float*)d_in[17];
  const float* g1_as  = (const float*)d_in[18];
  const float* g1_ad  = (const float*)d_in[19];
  const float* g1_b   = (const float*)d_in[20];
  const float* bn1_g  = (const float*)d_in[21];
  const float* bn1_b  = (const float*)d_in[22];
  const float* f0_w   = (const float*)d_in[23];
  const float* f0_b   = (const float*)d_in[24];
  const float* fbn0_g = (const float*)d_in[25];
  const float* fbn0_b = (const float*)d_in[26];
  const float* f1_w   = (const float*)d_in[27];
  const float* f1_b   = (const float*)d_in[28];
  const float* fbn1_g = (const float*)d_in[29];
  const float* fbn1_b = (const float*)d_in[30];
  float* out = (float*)d_out;

  k_lin12<<<Nn/32, 256>>>(x, il_w1, il_b1, il_g1, il_be1,
                          il_w2, il_b2, il_g2, il_be2, lp_A);
  k_feat<DIN, false><<<dim3(Nn/16, NH), 128>>>(x, g0_w, g0_as, g0_ad);
  k_zacc<<<(Nn*HF/4 + 255)/256, 256>>>();
  k_score<<<dim3(Nn/64, Nn/64), 256>>>(out, lp_b);              // ncu probe slot
  k_top2<<<Nn/8, 256>>>(out);
  k_edges<<<ET/256, 256>>>(out);
  // GAT layer 0
  k_agg<<<(ET*32)/256, 256>>>();
  k_fin<<<Nn/2, 256>>>(g0_b, bn0_g, bn0_b);                     // self-cleans for L1
  // GAT layer 1
  k_feat<DHID, true><<<dim3(Nn/16, NH), 128>>>(x, g1_w, g1_as, g1_ad);
  k_agg<<<(ET*32)/256, 256>>>();
  k_fin<<<Nn/2, 256>>>(g1_b, bn1_g, bn1_b);
  // fused output heads
  k_out<<<Nn/32, 256>>>(out, f0_w, f0_b, fbn0_g, fbn0_b,
                        f1_w, f1_b, fbn1_g, fbn1_b);
}

// round 17
// speedup vs baseline: 1.1004x; 1.0529x over previous
#include <cuda_runtime.h>
#include <math.h>

#define Nn 8192
#define DIN 64
#define DHID 128
#define DE 16
#define NH 4
#define TOPK 7
#define EK (Nn*TOPK)
#define ET (EK+Nn)
#define HF (NH*DHID)
#define BNS 0.9999950000374997f

#define OUT0_OFF 0
#define OUT1_OFF (Nn*64)
#define EI_OFF (OUT1_OFF + Nn*16)
#define LL_OFF (EI_OFF + 2*ET)

// -------- device scratch (no allocs allowed) --------
__device__ float g_M[Nn*Nn];          // lower triangle only is written/read
__device__ float g_M1[Nn*128];        // per-row per-64col-tile maxes (4 MiB)
__device__ float g_emb[Nn*DE];
__device__ float g_P[Nn*DE];
__device__ int   g_sel[Nn*TOPK];
__device__ int   g_src[ET];
__device__ int   g_dst[ET];
__device__ int   g_val[ET];
__device__ float g_hlin[Nn*HF];
__device__ float g_asrc[Nn*NH];
__device__ float g_adst[Nn*NH];
__device__ float g_acc[Nn*HF];        // zeroed by k_zacc (launch start) + k_fin self-clean
__device__ float g_den[Nn*NH];
__device__ float g_h[Nn*DHID];

__device__ __forceinline__ float eluf(float x){ return x > 0.f ? x : expm1f(x); }

// sorted top-7 insert (descending value, ties -> lower index)
__device__ __forceinline__ void ins7(float (&tv)[TOPK], int (&tix)[TOPK], float v, int j){
  if (v > tv[TOPK-1] || (v == tv[TOPK-1] && j < tix[TOPK-1])){
    float cv = v; int ci = j;
    #pragma unroll
    for (int s = 0; s < TOPK; s++){
      bool bt = (cv > tv[s]) || (cv == tv[s] && ci < tix[s]);
      float nv = bt ? cv : tv[s]; int ni = bt ? ci : tix[s];
      cv = bt ? tv[s] : cv; ci = bt ? tix[s] : ci;
      tv[s] = nv; tix[s] = ni;
    }
  }
}

// warp-merge sorted per-lane lists -> global top-7 indices, write to selp
__device__ __forceinline__ void wmerge7(float (&tv)[TOPK], int (&tix)[TOPK],
                                        int lane, int* selp){
  #pragma unroll 1
  for (int k = 0; k < TOPK; k++){
    float bv = tv[0]; int bi = tix[0];
    #pragma unroll
    for (int m = 16; m; m >>= 1){
      float ov = __shfl_xor_sync(0xffffffffu, bv, m);
      int   oi = __shfl_xor_sync(0xffffffffu, bi, m);
      if (ov > bv || (ov == bv && oi < bi)){ bv = ov; bi = oi; }
    }
    if (lane == 0) selp[k] = bi;
    if (tv[0] == bv && tix[0] == bi){
      #pragma unroll
      for (int s = 0; s < TOPK-1; s++){ tv[s] = tv[s+1]; tix[s] = tix[s+1]; }
      tv[TOPK-1] = -3.4e38f; tix[TOPK-1] = 0x7fffffff;
    }
  }
}

// -------- zero accumulators (start of every replay -> stateless) --------
__global__ void __launch_bounds__(256) k_zacc(){
  int t = blockIdx.x*256 + threadIdx.x;
  float4* a4 = (float4*)g_acc;
  if (t < (Nn*HF)/4) a4[t] = make_float4(0.f, 0.f, 0.f, 0.f);
  if (t < Nn*NH) g_den[t] = 0.f;
}

// -------- fused initial MLP: x -> tmp128 -> emb, P  (32 rows/block) --------
__global__ void __launch_bounds__(256) k_lin12(const float* __restrict__ x,
    const float* __restrict__ w1, const float* __restrict__ b1,
    const float* __restrict__ g1, const float* __restrict__ be1,
    const float* __restrict__ w2, const float* __restrict__ b2,
    const float* __restrict__ g2, const float* __restrict__ be2,
    const float* __restrict__ lpA){
  __shared__ float xs[32][DIN+1];
  __shared__ float t128[32][DHID+1];
  __shared__ float es[32][DE+1];
  int r0 = blockIdx.x*32, tid = threadIdx.x;
  for (int idx = tid; idx < 32*DIN; idx += 256) xs[idx/DIN][idx%DIN] = x[r0*DIN + idx];
  __syncthreads();
  {
    int c = tid & 127, rg = tid >> 7;
    float acc[16];
    #pragma unroll
    for (int k = 0; k < 16; k++) acc[k] = 0.f;
    for (int d = 0; d < DIN; d++){
      float wv = w1[d*DHID + c];
      #pragma unroll
      for (int k = 0; k < 16; k++) acc[k] += xs[rg + 2*k][d]*wv;
    }
    float bv = b1[c], gv = g1[c], bev = be1[c];
    #pragma unroll
    for (int k = 0; k < 16; k++)
      t128[rg + 2*k][c] = eluf(gv*(acc[k] + bv)*BNS + bev);
  }
  __syncthreads();
  int rr = tid >> 4, cc = tid & 15;
  #pragma unroll
  for (int half = 0; half < 2; half++){
    int row = rr + 16*half;
    float a2 = b2[cc];
    #pragma unroll 8
    for (int d = 0; d < DHID; d++) a2 += t128[row][d]*w2[d*DE + cc];
    a2 = eluf(g2[cc]*a2*BNS + be2[cc]);
    es[row][cc] = a2;
    g_emb[(r0+row)*DE + cc] = a2;
  }
  __syncthreads();
  #pragma unroll
  for (int half = 0; half < 2; half++){
    int row = rr + 16*half;
    float p = 0.f;
    #pragma unroll
    for (int d = 0; d < DE; d++) p += es[row][d]*lpA[d*DE + cc];
    g_P[(r0+row)*DE + cc] = p;
  }
}

// -------- score tiles: upper-tri 64x64; write ll, M-lower, tile-maxes M1 --------
__global__ void __launch_bounds__(256) k_score(float* __restrict__ out,
                                               const float* __restrict__ lp_b){
  int jt = blockIdx.x, it = blockIdx.y;
  if (it > jt) return;
  __shared__ float Pt[64][16];
  __shared__ float Es[16][68];
  __shared__ float ts[64][68];
  __shared__ float rmx[64];
  __shared__ float cmx[4][64];
  int i0 = it*64, j0 = jt*64;
  int t = threadIdx.x;
  const float4* pF = (const float4*)g_P;
  const float4* eF = (const float4*)g_emb;
  {
    int r = t >> 2, q = t & 3;
    *(float4*)&Pt[r][q*4] = pF[(i0+r)*4 + q];
    float4 ev = eF[(j0+r)*4 + q];
    Es[q*4+0][r] = ev.x; Es[q*4+1][r] = ev.y;
    Es[q*4+2][r] = ev.z; Es[q*4+3][r] = ev.w;
  }
  __syncthreads();
  int tr = t >> 4, tc = t & 15;
  float acc[4][4];
  #pragma unroll
  for (int a = 0; a < 4; a++)
    #pragma unroll
    for (int k = 0; k < 4; k++) acc[a][k] = 0.f;
  #pragma unroll
  for (int dg = 0; dg < 4; dg++){
    float4 e0 = *(const float4*)&Es[dg*4+0][tc*4];
    float4 e1 = *(const float4*)&Es[dg*4+1][tc*4];
    float4 e2 = *(const float4*)&Es[dg*4+2][tc*4];
    float4 e3 = *(const float4*)&Es[dg*4+3][tc*4];
    #pragma unroll
    for (int a = 0; a < 4; a++){
      float4 p = *(const float4*)&Pt[tr*4+a][dg*4];
      acc[a][0] += p.x*e0.x + p.y*e1.x + p.z*e2.x + p.w*e3.x;
      acc[a][1] += p.x*e0.y + p.y*e1.y + p.z*e2.y + p.w*e3.y;
      acc[a][2] += p.x*e0.z + p.y*e1.z + p.z*e2.z + p.w*e3.z;
      acc[a][3] += p.x*e0.w + p.y*e1.w + p.z*e2.w + p.w*e3.w;
    }
  }
  float bb = lp_b[0];
  #pragma unroll
  for (int a = 0; a < 4; a++)
    #pragma unroll
    for (int k = 0; k < 4; k++) acc[a][k] += bb;

  bool diag = (it == jt);
  float* ll = out + LL_OFF;

  #pragma unroll
  for (int a = 0; a < 4; a++){
    int R = tr*4 + a;
    float rm = -3.4e38f;
    #pragma unroll
    for (int k = 0; k < 4; k++){
      int C = tc*4 + k;
      float v = (diag && C <= R) ? -3.4e38f : acc[a][k];
      rm = fmaxf(rm, v);
    }
    #pragma unroll
    for (int m = 1; m < 16; m <<= 1)
      rm = fmaxf(rm, __shfl_xor_sync(0xffffffffu, rm, m));
    if (tc == 0){
      if (diag) rmx[R] = rm;
      else g_M1[(size_t)(i0+R)*128 + jt] = rm;
    }
  }

  #pragma unroll
  for (int a = 0; a < 4; a++){
    int i = i0 + tr*4 + a;
    int bi = i*(Nn-1) - (i*(i-1))/2 - i - 1;
    if (!diag){
      #pragma unroll
      for (int k = 0; k < 4; k++) ll[bi + j0 + tc*4 + k] = acc[a][k];
    } else {
      #pragma unroll
      for (int k = 0; k < 4; k++){
        int j = j0 + tc*4 + k;
        if (j > i) ll[bi + j] = acc[a][k];
      }
    }
    #pragma unroll
    for (int k = 0; k < 4; k++){
      int R = tr*4 + a, C = tc*4 + k;
      ts[R][C] = (diag && C <= R) ? -3.4e38f : acc[a][k];
    }
  }
  __syncthreads();
  #pragma unroll
  for (int a = 0; a < 4; a++){
    int jr = j0 + tr*4 + a;
    float w0 = ts[tc*4+0][tr*4+a];
    float w1 = ts[tc*4+1][tr*4+a];
    float w2 = ts[tc*4+2][tr*4+a];
    float w3 = ts[tc*4+3][tr*4+a];
    if (!diag){
      *(float4*)&g_M[(size_t)jr*Nn + i0 + tc*4] = make_float4(w0, w1, w2, w3);
    } else {
      float wv[4] = {w0, w1, w2, w3};
      #pragma unroll
      for (int k = 0; k < 4; k++){
        int ic = i0 + tc*4 + k;
        if (jr > ic) g_M[(size_t)jr*Nn + ic] = wv[k];
      }
    }
  }
  {
    int colc = t & 63, part = t >> 6;
    float cm = -3.4e38f;
    #pragma unroll
    for (int r = 0; r < 16; r++) cm = fmaxf(cm, ts[part*16 + r][colc]);
    cmx[part][colc] = cm;
  }
  __syncthreads();
  if (t < 64){
    float cmax = fmaxf(fmaxf(cmx[0][t], cmx[1][t]), fmaxf(cmx[2][t], cmx[3][t]));
    if (diag) g_M1[(size_t)(i0+t)*128 + it] = fmaxf(rmx[t], cmax);
    else      g_M1[(size_t)(j0+t)*128 + it] = cmax;
  }
}

// -------- top-7 per row via tile-max prefilter; warp per row --------
__global__ void __launch_bounds__(256) k_top2(const float* __restrict__ out){
  int row = (blockIdx.x*blockDim.x + threadIdx.x) >> 5;
  int lane = threadIdx.x & 31;
  float4 tm = *((const float4*)(g_M1 + (size_t)row*128) + lane);
  float tv[TOPK]; int tix[TOPK];
  #pragma unroll
  for (int s = 0; s < TOPK; s++){ tv[s] = -3.4e38f; tix[s] = 0x7fffffff; }
  ins7(tv, tix, tm.x, lane*4+0);
  ins7(tv, tix, tm.y, lane*4+1);
  ins7(tv, tix, tm.z, lane*4+2);
  ins7(tv, tix, tm.w, lane*4+3);
  float m7 = -3.4e38f;
  #pragma unroll 1
  for (int k = 0; k < TOPK; k++){
    float bv = tv[0]; int bi = tix[0];
    #pragma unroll
    for (int m = 16; m; m >>= 1){
      float ov = __shfl_xor_sync(0xffffffffu, bv, m);
      int   oi = __shfl_xor_sync(0xffffffffu, bi, m);
      if (ov > bv || (ov == bv && oi < bi)){ bv = ov; bi = oi; }
    }
    m7 = bv;
    if (tv[0] == bv && tix[0] == bi){
      #pragma unroll
      for (int s = 0; s < TOPK-1; s++){ tv[s] = tv[s+1]; tix[s] = tix[s+1]; }
      tv[TOPK-1] = -3.4e38f; tix[TOPK-1] = 0x7fffffff;
    }
  }
  unsigned bq[4];
  bq[0] = __ballot_sync(0xffffffffu, tm.x >= m7);
  bq[1] = __ballot_sync(0xffffffffu, tm.y >= m7);
  bq[2] = __ballot_sync(0xffffffffu, tm.z >= m7);
  bq[3] = __ballot_sync(0xffffffffu, tm.w >= m7);
  float tv2[TOPK]; int ti2[TOPK];
  #pragma unroll
  for (int s = 0; s < TOPK; s++){ tv2[s] = -3.4e38f; ti2[s] = 0x7fffffff; }
  const float* Mr = g_M + (size_t)row*Nn;
  const float* ll = out + LL_OFF;
  int bi = row*(Nn-1) - (row*(row-1))/2 - row - 1;
  #pragma unroll 1
  for (int q = 0; q < 4; q++){
    unsigned b = bq[q];
    while (b){
      int l = __ffs(b) - 1; b &= b - 1;
      int T = l*4 + q;
      int j1 = T*64 + lane;
      int j2 = j1 + 32;
      float v1 = (j1 < row) ? Mr[j1] : (j1 > row ? ll[bi + j1] : -3.4e38f);
      float v2 = (j2 < row) ? Mr[j2] : (j2 > row ? ll[bi + j2] : -3.4e38f);
      ins7(tv2, ti2, v1, j1);
      ins7(tv2, ti2, v2, j2);
    }
  }
  wmerge7(tv2, ti2, lane, &g_sel[row*TOPK]);
}

// -------- edge build + dedup + edge_index output --------
__global__ void k_edges(float* __restrict__ out){
  int e = blockIdx.x*256 + threadIdx.x;
  if (e >= ET) return;
  int s, d, valid = 1;
  if (e < EK){
    int i = e / TOPK;
    int j = g_sel[e];
    if (j < i){
      #pragma unroll
      for (int kk = 0; kk < TOPK; kk++)
        if (g_sel[j*TOPK + kk] == i) valid = 0;
    }
    s = min(i, j); d = max(i, j);
  } else {
    s = d = e - EK;
  }
  g_src[e] = s; g_dst[e] = d; g_val[e] = valid;
  out[EI_OFF + e]      = (float)s;
  out[EI_OFF + ET + e] = (float)d;
}

// -------- feature GEMM + fused attention dots, broadcast-smem version --------
// block = 64 rows x 1 head (grid Nn/64 x NH). Thread = 8 rows x 4 cols.
// All lanes of a warp share rows -> fsT reads are broadcast LDS; W reads are
// coalesced __ldg float4 (L1-cached across the 8 warps). d-ascending FMA order
// per output preserved (bitwise identical hlin).
template<int KD, bool USE_GH>
__global__ void __launch_bounds__(256) k_feat(const float* __restrict__ xin,
                                              const float* __restrict__ W,
                                              const float* __restrict__ as,
                                              const float* __restrict__ ad){
  __shared__ float fsT[KD][68];
  const float* feat = USE_GH ? g_h : xin;
  int r0 = blockIdx.x*64, tid = threadIdx.x;
  int h = blockIdx.y;
  for (int idx = tid; idx < 64*KD; idx += 256){
    int r = idx / KD, d = idx % KD;
    fsT[d][r] = feat[(r0+r)*KD + d];
  }
  __syncthreads();
  int cg = tid & 31, rg = tid >> 5;       // warp rg owns rows rg*8..+7
  float acc[8][4];
  #pragma unroll
  for (int r = 0; r < 8; r++)
    #pragma unroll
    for (int k = 0; k < 4; k++) acc[r][k] = 0.f;
  for (int d = 0; d < KD; d++){
    float4 w = __ldg((const float4*)(W + (size_t)d*HF + h*128) + cg);
    float4 fa = *(const float4*)&fsT[d][rg*8];
    float4 fb = *(const float4*)&fsT[d][rg*8 + 4];
    float fr[8] = {fa.x, fa.y, fa.z, fa.w, fb.x, fb.y, fb.z, fb.w};
    #pragma unroll
    for (int r = 0; r < 8; r++){
      acc[r][0] += fr[r]*w.x; acc[r][1] += fr[r]*w.y;
      acc[r][2] += fr[r]*w.z; acc[r][3] += fr[r]*w.w;
    }
  }
  #pragma unroll
  for (int r = 0; r < 8; r++)
    *(float4*)&g_hlin[(size_t)(r0 + rg*8 + r)*HF + h*128 + cg*4] =
      make_float4(acc[r][0], acc[r][1], acc[r][2], acc[r][3]);
  // fused attention coefficients: full 128-col dot per row via warp reduce
  float4 asv = __ldg((const float4*)(as + h*DHID) + cg);
  float4 adv = __ldg((const float4*)(ad + h*DHID) + cg);
  #pragma unroll
  for (int r = 0; r < 8; r++){
    float p1 = acc[r][0]*asv.x + acc[r][1]*asv.y + acc[r][2]*asv.z + acc[r][3]*asv.w;
    float p2 = acc[r][0]*adv.x + acc[r][1]*adv.y + acc[r][2]*adv.z + acc[r][3]*adv.w;
    #pragma unroll
    for (int m = 16; m; m >>= 1){
      p1 += __shfl_xor_sync(0xffffffffu, p1, m);
      p2 += __shfl_xor_sync(0xffffffffu, p2, m);
    }
    if (cg == 0){
      int n = r0 + rg*8 + r;
      g_asrc[n*NH + h] = p1;
      g_adst[n*NH + h] = p2;
    }
  }
}

// -------- edge-parallel aggregation: warp per edge, vector red.v4 --------
__global__ void __launch_bounds__(256) k_agg(){
  int e = (blockIdx.x*256 + threadIdx.x) >> 5;
  int lane = threadIdx.x & 31;
  if (e >= ET || !__ldg(&g_val[e])) return;
  int s = __ldg(&g_src[e]), d = __ldg(&g_dst[e]);
  float w[NH];
  #pragma unroll
  for (int h = 0; h < NH; h++){
    float al = __ldg(&g_asrc[s*NH + h]) + __ldg(&g_adst[d*NH + h]);
    al = al > 0.f ? al : 0.2f*al;
    w[h] = expf(al);
  }
  if (lane < NH) atomicAdd(&g_den[d*NH + lane], w[lane]);
  const float4* hp = (const float4*)(g_hlin + (size_t)s*HF);
  float* ap = g_acc + (size_t)d*HF;
  #pragma unroll
  for (int t = 0; t < 4; t++){
    float4 hv = __ldg(&hp[lane + 32*t]);
    float ww = w[t];
    asm volatile("red.global.add.v4.f32 [%0], {%1, %2, %3, %4};"
      :: "l"(ap + t*128 + lane*4),
         "f"(hv.x*ww), "f"(hv.y*ww), "f"(hv.z*ww), "f"(hv.w*ww)
      : "memory");
  }
}

// -------- finalize + self-clean acc/den (covered by replay-start k_zacc) --------
__global__ void __launch_bounds__(256) k_fin(const float* __restrict__ bias,
                                             const float* __restrict__ bng,
                                             const float* __restrict__ bnb){
  int n = blockIdx.x*2 + (threadIdx.x >> 7);
  int f = threadIdx.x & 127;
  float s = 0.f;
  #pragma unroll
  for (int h = 0; h < NH; h++)
    s += g_acc[(size_t)n*HF + h*DHID + f] / g_den[n*NH + h];
  float o = s*0.25f + bias[f];
  o = bng[f]*o*BNS + bnb[f];
  g_h[n*DHID + f] = eluf(o);
  #pragma unroll
  for (int h = 0; h < NH; h++) g_acc[(size_t)n*HF + h*DHID + f] = 0.f;
  __syncthreads();
  if (f < NH) g_den[n*NH + f] = 0.f;
}

// -------- fused output heads: out0 = bn(h@f0+b), out1 = bn(elu(out0@f1+b)) --------
__global__ void __launch_bounds__(256) k_out(float* __restrict__ out,
    const float* __restrict__ f0w, const float* __restrict__ f0b,
    const float* __restrict__ bg0, const float* __restrict__ bb0,
    const float* __restrict__ f1w, const float* __restrict__ f1b,
    const float* __restrict__ bg1, const float* __restrict__ bb1){
  __shared__ float hs[32][DHID+1];
  __shared__ float o0[32][65];
  int r0 = blockIdx.x*32, tid = threadIdx.x;
  for (int idx = tid; idx < 32*DHID; idx += 256)
    hs[idx/DHID][idx%DHID] = g_h[r0*DHID + idx];
  __syncthreads();
  {
    int c = tid & 63, rg = tid >> 6;
    float acc[8];
    #pragma unroll
    for (int k = 0; k < 8; k++) acc[k] = 0.f;
    for (int d = 0; d < DHID; d++){
      float wv = f0w[d*64 + c];
      #pragma unroll
      for (int k = 0; k < 8; k++) acc[k] += hs[rg + 4*k][d]*wv;
    }
    float bv = f0b[c], gv = bg0[c], bbv = bb0[c];
    #pragma unroll
    for (int k = 0; k < 8; k++){
      float a = gv*(acc[k] + bv)*BNS + bbv;
      out[OUT0_OFF + (r0 + rg + 4*k)*64 + c] = a;
      o0[rg + 4*k][c] = a;
    }
  }
  __syncthreads();
  int rr = tid >> 4, cc = tid & 15;
  #pragma unroll
  for (int half = 0; half < 2; half++){
    int row = rr + 16*half;
    float a = f1b[cc];
    #pragma unroll 8
    for (int d = 0; d < 64; d++) a += o0[row][d]*f1w[d*DE + cc];
    a = eluf(a);
    a = bg1[cc]*a*BNS + bb1[cc];
    out[OUT1_OFF + (r0+row)*DE + cc] = a;
  }
}

extern "C" void kernel_launch(void* const* d_in, const int* in_sizes, int n_in,
                              void* d_out, int out_size) {
  const float* x      = (const float*)d_in[0];
  const float* il_w1  = (const float*)d_in[1];
  const float* il_b1  = (const float*)d_in[2];
  const float* il_g1  = (const float*)d_in[3];
  const float* il_be1 = (const float*)d_in[4];
  const float* il_w2  = (const float*)d_in[5];
  const float* il_b2  = (const float*)d_in[6];
  const float* il_g2  = (const float*)d_in[7];
  const float* il_be2 = (const float*)d_in[8];
  const float* lp_A   = (const float*)d_in[9];
  const float* lp_b   = (const float*)d_in[10];
  const float* g0_w   = (const float*)d_in[11];
  const float* g0_as  = (const float*)d_in[12];
  const float* g0_ad  = (const float*)d_in[13];
  const float* g0_b   = (const float*)d_in[14];
  const float* bn0_g  = (const float*)d_in[15];
  const float* bn0_b  = (const float*)d_in[16];
  const float* g1_w   = (const float*)d_in[17];
  const float* g1_as  = (const float*)d_in[18];
  const float* g1_ad  = (const float*)d_in[19];
  const float* g1_b   = (const float*)d_in[20];
  const float* bn1_g  = (const float*)d_in[21];
  const float* bn1_b  = (const float*)d_in[22];
  const float* f0_w   = (const float*)d_in[23];
  const float* f0_b   = (const float*)d_in[24];
  const float* fbn0_g = (const float*)d_in[25];
  const float* fbn0_b = (const float*)d_in[26];
  const float* f1_w   = (const float*)d_in[27];
  const float* f1_b   = (const float*)d_in[28];
  const float* fbn1_g = (const float*)d_in[29];
  const float* fbn1_b = (const float*)d_in[30];
  float* out = (float*)d_out;

  k_lin12<<<Nn/32, 256>>>(x, il_w1, il_b1, il_g1, il_be1,
                          il_w2, il_b2, il_g2, il_be2, lp_A);
  k_feat<DIN, false><<<dim3(Nn/64, NH), 256>>>(x, g0_w, g0_as, g0_ad);
  k_zacc<<<(Nn*HF/4 + 255)/256, 256>>>();
  k_score<<<dim3(Nn/64, Nn/64), 256>>>(out, lp_b);              // ncu probe slot
  k_top2<<<Nn/8, 256>>>(out);
  k_edges<<<ET/256, 256>>>(out);
  // GAT layer 0
  k_agg<<<(ET*32)/256, 256>>>();
  k_fin<<<Nn/2, 256>>>(g0_b, bn0_g, bn0_b);
  // GAT layer 1
  k_feat<DHID, true><<<dim3(Nn/64, NH), 256>>>(x, g1_w, g1_as, g1_ad);
  k_agg<<<(ET*32)/256, 256>>>();
  k_fin<<<Nn/2, 256>>>(g1_b, bn1_g, bn1_b);
  // fused output heads
  k_out<<<Nn/32, 256>>>(out, f0_w, f0_b, fbn0_g, fbn0_b,
                        f1_w, f1_b, fbn1_g, fbn1_b);
}